// round 1
// baseline (speedup 1.0000x reference)
#include <cuda_runtime.h>
#include <math.h>

// Inputs (metadata order):
// 0 tag_ids[386] i32, 1 word_ids[386] i32, 2 tag_emb[50,128], 3 word_emb[10000,384],
// 4 Wf_ih[2048,512], 5 Wf_hh[2048,512], 6 bf[2048], 7 Wb_ih[2048,512], 8 Wb_hh[2048,512], 9 bb[2048],
// 10 W1[1024,1024], 11 b1[1024], 12 W2[1024,128], 13 b2[128],
// 14 V1[1024,1024], 15 c1[1024], 16 V2[1024,1], 17 c2[1]
// Output: [73920, 129] f32

#define TT 386
#define HH 512
#define G4 2048
#define NP1 385
#define OUTC 129
#define LSTM_BD 32   // blocks per direction

// ------------- device scratch (no mallocs allowed) -------------
__device__ float d_x[TT * 512];
__device__ float d_gx[2][TT * G4];
__device__ float d_states[2][TT * HH];   // [0]=fwd[t], [1]=bwd[t] (original time index)
__device__ float d_hbuf[2][HH];
__device__ unsigned int d_ctr[2];
__device__ float d_E[NP1 * 1024];
__device__ float d_F[NP1 * 1024];

static __device__ __forceinline__ float4 f4add(float4 a, float4 b) {
    return make_float4(a.x + b.x, a.y + b.y, a.z + b.z, a.w + b.w);
}
static __device__ __forceinline__ float4 f4sub(float4 a, float4 b) {
    return make_float4(a.x - b.x, a.y - b.y, a.z - b.z, a.w - b.w);
}
static __device__ __forceinline__ float4 f4relu(float4 a) {
    return make_float4(fmaxf(a.x, 0.f), fmaxf(a.y, 0.f), fmaxf(a.z, 0.f), fmaxf(a.w, 0.f));
}

// ---------------- embed: x[t] = [tag_emb[tag], word_emb[word]] ----------------
__global__ void embed_kernel(const int* __restrict__ tag_ids, const int* __restrict__ word_ids,
                             const float* __restrict__ tag_emb, const float* __restrict__ word_emb) {
    int t = blockIdx.x;
    int tid = threadIdx.x;  // 128 threads: 128 float4 = 512 floats
    int tg = tag_ids[t], wd = word_ids[t];
    float4 v;
    if (tid < 32) v = ((const float4*)(tag_emb + (size_t)tg * 128))[tid];
    else          v = ((const float4*)(word_emb + (size_t)wd * 384))[tid - 32];
    ((float4*)(d_x + (size_t)t * 512))[tid] = v;
}

// ---------------- gx = x @ W_ih^T + b,  both directions ----------------
// grid: (32 jtiles of 64, 13 ttiles of 32, 2 dirs), 256 threads
__global__ __launch_bounds__(256) void gx_kernel(const float* __restrict__ Wf, const float* __restrict__ bfv,
                                                 const float* __restrict__ Wb, const float* __restrict__ bbv) {
    int dir = blockIdx.z;
    const float* W = dir ? Wb : Wf;
    const float* bias = dir ? bbv : bfv;
    int j0 = blockIdx.x * 64;
    int t0 = blockIdx.y * 32;
    __shared__ float xs[32][65];
    __shared__ float ws[64][65];
    int tid = threadIdx.x;
    int tt = tid >> 5, tj = tid & 31;
    float acc[4][2] = {};
    for (int kc = 0; kc < 8; kc++) {
#pragma unroll
        for (int i = 0; i < 2; i++) {
            int fi = tid + i * 256;           // 512 float4 of x tile
            int row = fi >> 4, q = fi & 15;
            float4 v = make_float4(0.f, 0.f, 0.f, 0.f);
            if (t0 + row < TT) v = *(const float4*)&d_x[(size_t)(t0 + row) * 512 + kc * 64 + q * 4];
            xs[row][q * 4 + 0] = v.x; xs[row][q * 4 + 1] = v.y;
            xs[row][q * 4 + 2] = v.z; xs[row][q * 4 + 3] = v.w;
        }
#pragma unroll
        for (int i = 0; i < 4; i++) {
            int fi = tid + i * 256;           // 1024 float4 of W tile [64j][64k]
            int j = fi >> 4, q = fi & 15;
            float4 v = *(const float4*)&W[(size_t)(j0 + j) * 512 + kc * 64 + q * 4];
            ws[j][q * 4 + 0] = v.x; ws[j][q * 4 + 1] = v.y;
            ws[j][q * 4 + 2] = v.z; ws[j][q * 4 + 3] = v.w;
        }
        __syncthreads();
#pragma unroll 8
        for (int kk = 0; kk < 64; kk++) {
            float b0 = ws[tj * 2 + 0][kk];
            float b1 = ws[tj * 2 + 1][kk];
#pragma unroll
            for (int i = 0; i < 4; i++) {
                float a = xs[tt * 4 + i][kk];
                acc[i][0] = fmaf(a, b0, acc[i][0]);
                acc[i][1] = fmaf(a, b1, acc[i][1]);
            }
        }
        __syncthreads();
    }
    float bj0 = bias[j0 + tj * 2 + 0];
    float bj1 = bias[j0 + tj * 2 + 1];
#pragma unroll
    for (int i = 0; i < 4; i++) {
        int t = t0 + tt * 4 + i;
        if (t < TT) {
            d_gx[dir][(size_t)t * G4 + j0 + tj * 2 + 0] = acc[i][0] + bj0;
            d_gx[dir][(size_t)t * G4 + j0 + tj * 2 + 1] = acc[i][1] + bj1;
        }
    }
}

// ---------------- counter reset (must precede LSTM each run) ----------------
__global__ void reset_kernel() { d_ctr[0] = 0u; d_ctr[1] = 0u; }

// ---------------- persistent bidirectional LSTM ----------------
// 64 blocks: [0,32) forward, [32,64) backward. 256 threads.
// Block bi owns h indices [bi*16, bi*16+16), i.e. 64 Whh rows (4 gates x 16),
// held entirely in registers (8 rows x 16 k per thread).
__global__ __launch_bounds__(256, 1) void lstm_kernel(const float* __restrict__ Wf_hh,
                                                      const float* __restrict__ Wb_hh) {
    int dir = blockIdx.x >> 5;
    int bi = blockIdx.x & 31;
    const float* Whh = dir ? Wb_hh : Wf_hh;
    int tid = threadIdx.x;
    int w = tid >> 5, s = tid & 31;

    __shared__ float4 hsm4[128];   // h_prev, 512 floats
    __shared__ float gsum[64];     // dot results, indexed rr = q*4+g
    __shared__ float gxsm[64];
    __shared__ float csm[16];

    // Load this thread's Whh slice into registers: rows rr=w*8+p, k = j*128 + s*4 + e
    float4 wreg[8][4];
#pragma unroll
    for (int p = 0; p < 8; p++) {
        int rr = w * 8 + p;
        int q = rr >> 2, g = rr & 3;
        int grow = g * 512 + bi * 16 + q;
#pragma unroll
        for (int j = 0; j < 4; j++)
            wreg[p][j] = *(const float4*)&Whh[(size_t)grow * 512 + j * 128 + s * 4];
    }
    if (tid < 16) csm[tid] = 0.f;
    volatile unsigned int* ctrv = &d_ctr[dir];

    for (int t = 0; t < TT; t++) {
        int ti = dir ? (TT - 1 - t) : t;
        if (tid < 128) {
            if (t == 0) hsm4[tid] = make_float4(0.f, 0.f, 0.f, 0.f);
            else        hsm4[tid] = __ldcg(((const float4*)&d_hbuf[dir][0]) + tid);
        }
        if (tid < 64) {
            int q = tid >> 2, g = tid & 3;
            gxsm[tid] = d_gx[dir][(size_t)ti * G4 + g * 512 + bi * 16 + q];
        }
        __syncthreads();

        float acc[8] = {0.f, 0.f, 0.f, 0.f, 0.f, 0.f, 0.f, 0.f};
#pragma unroll
        for (int j = 0; j < 4; j++) {
            float4 hv = hsm4[j * 32 + s];
#pragma unroll
            for (int p = 0; p < 8; p++) {
                float4 wv = wreg[p][j];
                acc[p] = fmaf(hv.x, wv.x, acc[p]);
                acc[p] = fmaf(hv.y, wv.y, acc[p]);
                acc[p] = fmaf(hv.z, wv.z, acc[p]);
                acc[p] = fmaf(hv.w, wv.w, acc[p]);
            }
        }
#pragma unroll
        for (int off = 16; off >= 1; off >>= 1) {
#pragma unroll
            for (int p = 0; p < 8; p++)
                acc[p] += __shfl_xor_sync(0xffffffffu, acc[p], off);
        }
        if (s < 8) {
            float v = acc[0];
            if (s == 1) v = acc[1]; else if (s == 2) v = acc[2]; else if (s == 3) v = acc[3];
            else if (s == 4) v = acc[4]; else if (s == 5) v = acc[5];
            else if (s == 6) v = acc[6]; else if (s == 7) v = acc[7];
            gsum[w * 8 + s] = v;
        }
        __syncthreads();

        if (tid < 16) {
            int q = tid;
            float gi = gsum[q * 4 + 0] + gxsm[q * 4 + 0];
            float gf = gsum[q * 4 + 1] + gxsm[q * 4 + 1];
            float gg = gsum[q * 4 + 2] + gxsm[q * 4 + 2];
            float go = gsum[q * 4 + 3] + gxsm[q * 4 + 3];
            float iv = 1.f / (1.f + __expf(-gi));
            float fv = 1.f / (1.f + __expf(-gf));
            float ov = 1.f / (1.f + __expf(-go));
            float c = fv * csm[q] + iv * tanhf(gg);
            float h = ov * tanhf(c);
            csm[q] = c;
            int hidx = bi * 16 + q;
            d_states[dir][(size_t)ti * HH + hidx] = h;
            __stcg(&d_hbuf[dir][hidx], h);
            __threadfence();
        }
        __syncwarp();
        if (tid == 0) {
            atomicAdd(&d_ctr[dir], 1u);
            unsigned int target = (unsigned)LSTM_BD * (unsigned)(t + 1);
            while (*ctrv < target) { }
            __threadfence();
        }
        __syncthreads();
    }
}

// ---------------- E/F precompute ----------------
// E[t] = fwd[t] @ W1[0:512] - bwd[t+1] @ W1[512:1024]   (t in 0..384)
// F likewise with V1. grid: (16 jtiles, 13 ttiles, 2 which), 256 threads.
__global__ __launch_bounds__(256) void e_kernel(const float* __restrict__ W1,
                                                const float* __restrict__ V1) {
    int which = blockIdx.z;
    const float* B = which ? V1 : W1;
    float* outp = which ? d_F : d_E;
    int j0 = blockIdx.x * 64;
    int t0 = blockIdx.y * 32;
    __shared__ float as_[32][65];
    __shared__ float ws[64][65];
    int tid = threadIdx.x;
    int tt = tid >> 5, tj = tid & 31;
    float acc[4][2] = {};
    for (int kc = 0; kc < 16; kc++) {
        int half = kc >> 3;            // 0: fwd (+), 1: bwd[t+1] (-)
        int koff = (kc & 7) * 64;
#pragma unroll
        for (int i = 0; i < 2; i++) {
            int fi = tid + i * 256;
            int row = fi >> 4, q = fi & 15;
            float4 v = make_float4(0.f, 0.f, 0.f, 0.f);
            int trow = t0 + row;
            if (trow < NP1) {
                const float* src = half ? &d_states[1][(size_t)(trow + 1) * HH + koff + q * 4]
                                        : &d_states[0][(size_t)trow * HH + koff + q * 4];
                v = *(const float4*)src;
                if (half) { v.x = -v.x; v.y = -v.y; v.z = -v.z; v.w = -v.w; }
            }
            as_[row][q * 4 + 0] = v.x; as_[row][q * 4 + 1] = v.y;
            as_[row][q * 4 + 2] = v.z; as_[row][q * 4 + 3] = v.w;
        }
#pragma unroll
        for (int i = 0; i < 4; i++) {
            int fi = tid + i * 256;        // W tile [64k][64j]
            int k = fi >> 4, q = fi & 15;
            float4 v = *(const float4*)&B[(size_t)(half * 512 + koff + k) * 1024 + j0 + q * 4];
            ws[k][q * 4 + 0] = v.x; ws[k][q * 4 + 1] = v.y;
            ws[k][q * 4 + 2] = v.z; ws[k][q * 4 + 3] = v.w;
        }
        __syncthreads();
#pragma unroll 8
        for (int kk = 0; kk < 64; kk++) {
            float b0 = ws[kk][tj * 2 + 0];
            float b1 = ws[kk][tj * 2 + 1];
#pragma unroll
            for (int i = 0; i < 4; i++) {
                float a = as_[tt * 4 + i][kk];
                acc[i][0] = fmaf(a, b0, acc[i][0]);
                acc[i][1] = fmaf(a, b1, acc[i][1]);
            }
        }
        __syncthreads();
    }
#pragma unroll
    for (int i = 0; i < 4; i++) {
        int t = t0 + tt * 4 + i;
        if (t < NP1) {
            outp[(size_t)t * 1024 + j0 + tj * 2 + 0] = acc[i][0];
            outp[(size_t)t * 1024 + j0 + tj * 2 + 1] = acc[i][1];
        }
    }
}

// ---------------- span kernel ----------------
// block = (l = blockIdx.y, 64 r's starting at r0). 256 threads (16 tr x 16 tc).
// h1 = relu(E[r] - E[l] + b1); out[:,0:128] = h1 @ W2 + b2
// h2 = relu(F[r] - F[l] + c1); out[:,128]   = h2 . V2 + c2
#define SPAN_SMEM_FLOATS (1024 + 1024 + 1024 + 128 + 64 * 68 + 64 * 68 + 64 * 128)
__global__ __launch_bounds__(256) void span_kernel(const float* __restrict__ b1,
                                                   const float* __restrict__ W2,
                                                   const float* __restrict__ b2,
                                                   const float* __restrict__ c1,
                                                   const float* __restrict__ V2,
                                                   const float* __restrict__ c2,
                                                   float* __restrict__ out) {
    int l = blockIdx.y;
    int r0 = l + 1 + blockIdx.x * 64;
    if (r0 > 384) return;
    int nr = min(64, 385 - r0);

    extern __shared__ float sm[];
    float* base1 = sm;                 // 1024 : b1 - E[l]
    float* baseV = sm + 1024;          // 1024 : c1 - F[l]
    float* v2s   = sm + 2048;          // 1024
    float* b2s   = sm + 3072;          // 128
    float* h1s   = sm + 3200;          // 64 x 68
    float* h2s   = h1s + 64 * 68;      // 64 x 68
    float* w2s   = h2s + 64 * 68;      // 64 x 128

    int tid = threadIdx.x;
    int tr = tid >> 4, tc = tid & 15;

    ((float4*)base1)[tid] = f4sub(((const float4*)b1)[tid], ((const float4*)&d_E[(size_t)l * 1024])[tid]);
    ((float4*)baseV)[tid] = f4sub(((const float4*)c1)[tid], ((const float4*)&d_F[(size_t)l * 1024])[tid]);
    ((float4*)v2s)[tid] = ((const float4*)V2)[tid];
    if (tid < 32) ((float4*)b2s)[tid] = ((const float4*)b2)[tid];
    __syncthreads();

    float acc[4][8] = {};
    float sacc[4] = {0.f, 0.f, 0.f, 0.f};
    long sbase = (long)l * 384 - (long)l * (l - 1) / 2 + (r0 - l - 1);

    for (int kc = 0; kc < 16; kc++) {
#pragma unroll
        for (int i = 0; i < 4; i++) {
            int fi = tid + i * 256;          // 1024 f4: 64 rows x 16 quads
            int row = fi >> 4, q = fi & 15;
            int k = kc * 64 + q * 4;
            float4 e = make_float4(0.f, 0.f, 0.f, 0.f), f = e;
            if (row < nr) {
                e = *(const float4*)&d_E[(size_t)(r0 + row) * 1024 + k];
                f = *(const float4*)&d_F[(size_t)(r0 + row) * 1024 + k];
            }
            float4 h1 = f4relu(f4add(e, *(const float4*)&base1[k]));
            float4 h2 = f4relu(f4add(f, *(const float4*)&baseV[k]));
            *(float4*)&h1s[row * 68 + q * 4] = h1;
            *(float4*)&h2s[row * 68 + q * 4] = h2;
        }
#pragma unroll
        for (int i = 0; i < 8; i++) {
            int fi = tid + i * 256;          // 2048 f4: W2 tile [64k][128n]
            int k = fi >> 5, q = fi & 31;
            *(float4*)&w2s[k * 128 + q * 4] = *(const float4*)&W2[(size_t)(kc * 64 + k) * 128 + q * 4];
        }
        __syncthreads();

#pragma unroll 4
        for (int kk = 0; kk < 64; kk++) {
            float4 bb0 = *(const float4*)&w2s[kk * 128 + tc * 8];
            float4 bb1 = *(const float4*)&w2s[kk * 128 + tc * 8 + 4];
#pragma unroll
            for (int i = 0; i < 4; i++) {
                float a = h1s[(tr * 4 + i) * 68 + kk];
                acc[i][0] = fmaf(a, bb0.x, acc[i][0]);
                acc[i][1] = fmaf(a, bb0.y, acc[i][1]);
                acc[i][2] = fmaf(a, bb0.z, acc[i][2]);
                acc[i][3] = fmaf(a, bb0.w, acc[i][3]);
                acc[i][4] = fmaf(a, bb1.x, acc[i][4]);
                acc[i][5] = fmaf(a, bb1.y, acc[i][5]);
                acc[i][6] = fmaf(a, bb1.z, acc[i][6]);
                acc[i][7] = fmaf(a, bb1.w, acc[i][7]);
            }
        }
        // split-score partial: thread covers kk = tc*4 + m
#pragma unroll
        for (int m = 0; m < 4; m++) {
            int kk = tc * 4 + m;
            float v = v2s[kc * 64 + kk];
#pragma unroll
            for (int i = 0; i < 4; i++)
                sacc[i] = fmaf(h2s[(tr * 4 + i) * 68 + kk], v, sacc[i]);
        }
        __syncthreads();
    }

    // reduce split partials over tc (16 lanes within half-warp)
#pragma unroll
    for (int off = 1; off < 16; off <<= 1) {
#pragma unroll
        for (int i = 0; i < 4; i++)
            sacc[i] += __shfl_xor_sync(0xffffffffu, sacc[i], off);
    }
    float c2v = c2[0];
#pragma unroll
    for (int i = 0; i < 4; i++) {
        int row = tr * 4 + i;
        if (row < nr) {
            long s = sbase + row;
            float* orow = out + s * (long)OUTC;
#pragma unroll
            for (int jj = 0; jj < 8; jj++)
                orow[tc * 8 + jj] = acc[i][jj] + b2s[tc * 8 + jj];
            if (tc == 0) orow[128] = sacc[i] + c2v;
        }
    }
}

// ---------------- launch ----------------
extern "C" void kernel_launch(void* const* d_in, const int* in_sizes, int n_in,
                              void* d_out, int out_size) {
    const int* tag_ids = (const int*)d_in[0];
    const int* word_ids = (const int*)d_in[1];
    const float* tag_emb = (const float*)d_in[2];
    const float* word_emb = (const float*)d_in[3];
    const float* Wf_ih = (const float*)d_in[4];
    const float* Wf_hh = (const float*)d_in[5];
    const float* bf = (const float*)d_in[6];
    const float* Wb_ih = (const float*)d_in[7];
    const float* Wb_hh = (const float*)d_in[8];
    const float* bb = (const float*)d_in[9];
    const float* W1 = (const float*)d_in[10];
    const float* b1 = (const float*)d_in[11];
    const float* W2 = (const float*)d_in[12];
    const float* b2 = (const float*)d_in[13];
    const float* V1 = (const float*)d_in[14];
    const float* c1 = (const float*)d_in[15];
    const float* V2 = (const float*)d_in[16];
    const float* c2 = (const float*)d_in[17];
    float* out = (float*)d_out;

    size_t span_smem = (size_t)SPAN_SMEM_FLOATS * sizeof(float);
    cudaFuncSetAttribute(span_kernel, cudaFuncAttributeMaxDynamicSharedMemorySize, (int)span_smem);

    embed_kernel<<<TT, 128>>>(tag_ids, word_ids, tag_emb, word_emb);

    dim3 ggx(32, 13, 2);
    gx_kernel<<<ggx, 256>>>(Wf_ih, bf, Wb_ih, bb);

    reset_kernel<<<1, 1>>>();
    lstm_kernel<<<64, 256>>>(Wf_hh, Wb_hh);

    dim3 ge(16, 13, 2);
    e_kernel<<<ge, 256>>>(W1, V1);

    dim3 gs(6, 384);
    span_kernel<<<gs, 256, span_smem>>>(b1, W2, b2, c1, V2, c2, out);

    (void)in_sizes; (void)n_in; (void)out_size;
}